// round 2
// baseline (speedup 1.0000x reference)
#include <cuda_runtime.h>
#include <math.h>

#define HH 512
#define WW 512
#define NB 2
#define HWSZ (HH*WW)          // 262144
#define NHW (NB*HWSZ)         // 524288
#define PARTS 128

// ---------------- scratch (device globals; no allocation allowed) -------------
__device__ float g_feat [NB*32*HWSZ];
__device__ float g_aux  [NB*32*HWSZ];
__device__ float g_auxb1[NB*32*HWSZ];
__device__ float g_z    [NHW];
__device__ float g_inp  [NHW];
__device__ float g_xm9  [NB*9*HWSZ];
__device__ float g_xm25 [NB*25*HWSZ];
__device__ float g_img2 [NB*3*HWSZ];
__device__ float g_part [32*PARTS*2];
__device__ float g_scale1[32], g_shift1[32];
__device__ float g_scale2[1],  g_shift2[1];
__device__ unsigned g_hist[4][256];
__device__ unsigned g_prefix[4];
__device__ int      g_remain[4];
__device__ float    g_thr[4];

// ---------------- generic 3x3 conv: tile 32x32, 8 oc x 4 rows per thread ------
template<int IC, bool RELU>
__global__ __launch_bounds__(256) void conv3x3_k(
    const float* __restrict__ in, const float* __restrict__ wt,
    float* __restrict__ out, int ocGroups)
{
    __shared__ float tile[34][34];
    __shared__ float wsm[8*IC*9];
    const int tid = threadIdx.y*32 + threadIdx.x;
    const int grp = blockIdx.z % ocGroups;
    const int n   = blockIdx.z / ocGroups;
    const int OC  = ocGroups*8;
    const int oc0 = grp*8;
    for (int i = tid; i < 8*IC*9; i += 256) wsm[i] = wt[oc0*IC*9 + i];
    const int x0 = blockIdx.x*32, y0 = blockIdx.y*32;
    float acc[8][4];
    #pragma unroll
    for (int o=0;o<8;o++)
        #pragma unroll
        for (int k=0;k<4;k++) acc[o][k]=0.f;

    for (int c = 0; c < IC; c++) {
        __syncthreads();
        for (int i = tid; i < 34*34; i += 256) {
            int yy = i/34, xx = i%34;
            int gy = y0+yy-1, gx = x0+xx-1;
            float v = 0.f;
            if ((unsigned)gy < HH && (unsigned)gx < WW)
                v = in[((size_t)(n*IC + c))*HWSZ + gy*WW + gx];
            tile[yy][xx] = v;
        }
        __syncthreads();
        #pragma unroll
        for (int r=0;r<3;r++)
        #pragma unroll
        for (int s=0;s<3;s++) {
            float wv[8];
            #pragma unroll
            for (int o=0;o<8;o++) wv[o] = wsm[(o*IC + c)*9 + r*3 + s];
            #pragma unroll
            for (int k=0;k<4;k++) {
                float v = tile[threadIdx.y + 8*k + r][threadIdx.x + s];
                #pragma unroll
                for (int o=0;o<8;o++) acc[o][k] = fmaf(wv[o], v, acc[o][k]);
            }
        }
    }
    #pragma unroll
    for (int o=0;o<8;o++)
    #pragma unroll
    for (int k=0;k<4;k++) {
        float v = acc[o][k];
        if (RELU) v = fmaxf(v, 0.f);
        out[((size_t)(n*OC + oc0 + o))*HWSZ + (size_t)(y0+threadIdx.y+8*k)*WW + x0 + threadIdx.x] = v;
    }
}

// ---------------- x1 = conv(feat, w_out) ; inp = x1 + relu(bn(z)) --------------
__global__ __launch_bounds__(256) void wout_inp_k(
    const float* __restrict__ feat, const float* __restrict__ wt)
{
    __shared__ float tile[34][34];
    __shared__ float wsm[32*9];
    const int tid = threadIdx.y*32 + threadIdx.x;
    const int n = blockIdx.z;
    for (int i = tid; i < 288; i += 256) wsm[i] = wt[i];   // FIXED: full 288 load
    const int x0 = blockIdx.x*32, y0 = blockIdx.y*32;
    float acc[4] = {0.f,0.f,0.f,0.f};
    for (int c = 0; c < 32; c++) {
        __syncthreads();
        for (int i = tid; i < 34*34; i += 256) {
            int yy = i/34, xx = i%34;
            int gy = y0+yy-1, gx = x0+xx-1;
            float v = 0.f;
            if ((unsigned)gy < HH && (unsigned)gx < WW)
                v = feat[((size_t)(n*32 + c))*HWSZ + gy*WW + gx];
            tile[yy][xx] = v;
        }
        __syncthreads();
        #pragma unroll
        for (int r=0;r<3;r++)
        #pragma unroll
        for (int s=0;s<3;s++) {
            float w = wsm[c*9 + r*3 + s];
            #pragma unroll
            for (int k=0;k<4;k++)
                acc[k] = fmaf(w, tile[threadIdx.y + 8*k + r][threadIdx.x + s], acc[k]);
        }
    }
    float s2 = g_scale2[0], h2 = g_shift2[0];
    #pragma unroll
    for (int k=0;k<4;k++) {
        int idx = (y0+threadIdx.y+8*k)*WW + x0 + threadIdx.x;
        float zz = g_z[(size_t)n*HWSZ + idx];
        g_inp[(size_t)n*HWSZ + idx] = acc[k] + fmaxf(zz*s2 + h2, 0.f);
    }
}

// ---------------- batchnorm stats (deterministic two-stage) -------------------
__global__ __launch_bounds__(256) void stats1_k(const float* __restrict__ in, int C)
{
    const int c = blockIdx.y, p = blockIdx.x;
    const int chunk = NHW / PARTS;
    const int base = p*chunk;
    float s = 0.f, q = 0.f;
    for (int i = base + threadIdx.x; i < base + chunk; i += 256) {
        int nn = i / HWSZ, r = i - nn*HWSZ;
        float v = in[((size_t)(nn*C + c))*HWSZ + r];
        s += v; q += v*v;
    }
    __shared__ float ss[256], qq[256];
    ss[threadIdx.x]=s; qq[threadIdx.x]=q;
    __syncthreads();
    for (int o=128;o>0;o>>=1){
        if (threadIdx.x < o){ ss[threadIdx.x]+=ss[threadIdx.x+o]; qq[threadIdx.x]+=qq[threadIdx.x+o]; }
        __syncthreads();
    }
    if (threadIdx.x==0){
        g_part[(c*PARTS+p)*2+0]=ss[0];
        g_part[(c*PARTS+p)*2+1]=qq[0];
    }
}

__global__ void stats2_k(const float* __restrict__ g, const float* __restrict__ b,
                         float* __restrict__ scale, float* __restrict__ shift)
{
    const int c = blockIdx.x;
    __shared__ float ss[128], qq[128];
    ss[threadIdx.x] = g_part[(c*PARTS+threadIdx.x)*2+0];
    qq[threadIdx.x] = g_part[(c*PARTS+threadIdx.x)*2+1];
    __syncthreads();
    for (int o=64;o>0;o>>=1){
        if (threadIdx.x < o){ ss[threadIdx.x]+=ss[threadIdx.x+o]; qq[threadIdx.x]+=qq[threadIdx.x+o]; }
        __syncthreads();
    }
    if (threadIdx.x==0){
        float mean = ss[0]/(float)NHW;
        float var  = qq[0]/(float)NHW - mean*mean;
        float sc = g[c]*rsqrtf(var + 1e-5f);
        scale[c]=sc; shift[c]=b[c]-mean*sc;
    }
}

// ---------------- z = sum_c relu(bn(auxb1_c)) * b2w_c --------------------------
__global__ __launch_bounds__(256) void b2_k(const float* __restrict__ w2)
{
    __shared__ float s[32], h[32], ww[32];
    if (threadIdx.x < 32){ s[threadIdx.x]=g_scale1[threadIdx.x];
                           h[threadIdx.x]=g_shift1[threadIdx.x];
                           ww[threadIdx.x]=w2[threadIdx.x]; }
    __syncthreads();
    int i = blockIdx.x*256 + threadIdx.x;
    if (i >= NHW) return;
    int n = i / HWSZ, r = i - n*HWSZ;
    float acc = 0.f;
    #pragma unroll
    for (int c=0;c<32;c++){
        float v = g_auxb1[((size_t)(n*32+c))*HWSZ + r];
        acc += fmaxf(v*s[c]+h[c], 0.f)*ww[c];
    }
    g_z[i] = acc;
}

// ---------------- xm9 = aff3(inp) + conv(inp, d0) ------------------------------
__global__ __launch_bounds__(256) void xm9_k(const float* __restrict__ d0)
{
    __shared__ float tile[10][34];
    __shared__ float wsm[81];
    const int n = blockIdx.z;
    const int x0 = blockIdx.x*32, y0 = blockIdx.y*8;
    const int tid = threadIdx.y*32 + threadIdx.x;
    if (tid < 81) wsm[tid] = d0[tid];
    for (int i = tid; i < 340; i += 256){
        int yy=i/34, xx=i%34;
        int gy=y0+yy-1, gx=x0+xx-1;
        tile[yy][xx] = ((unsigned)gy<HH && (unsigned)gx<WW) ? g_inp[(size_t)n*HWSZ + gy*WW + gx] : 0.f;
    }
    __syncthreads();
    float nb[3][3];
    #pragma unroll
    for (int r=0;r<3;r++)
    #pragma unroll
    for (int s=0;s<3;s++) nb[r][s] = tile[threadIdx.y+r][threadIdx.x+s];
    float ctr = nb[1][1];
    int idx = (y0+threadIdx.y)*WW + x0 + threadIdx.x;
    #pragma unroll
    for (int t=0;t<9;t++){
        int ii=t/3, jj=t%3;
        float cv=0.f;
        #pragma unroll
        for (int r=0;r<3;r++)
        #pragma unroll
        for (int s=0;s<3;s++) cv = fmaf(nb[r][s], wsm[t*9+r*3+s], cv);
        g_xm9[((size_t)(n*9+t))*HWSZ + idx] = fmaf(nb[ii][jj], ctr, cv);
    }
}

// ---------------- xm25 = aff5(inp) + conv(xm9, d1) -----------------------------
// block (8,8); 4 px/thread along x; grid.z = N*5 (t-group of 5, row offset i=grp)
__global__ __launch_bounds__(64) void xm25_k(const float* __restrict__ d1)
{
    __shared__ float t9[10][34];
    __shared__ float ti[12][36];
    __shared__ float wsm[5*81];
    const int grp = blockIdx.z % 5, n = blockIdx.z / 5;
    const int x0 = blockIdx.x*32, y0 = blockIdx.y*8;
    const int tid = threadIdx.y*8 + threadIdx.x;
    for (int i=tid;i<405;i+=64) wsm[i] = d1[(size_t)(grp*5)*81 + i];
    for (int i=tid;i<432;i+=64){
        int yy=i/36, xx=i%36;
        int gy=y0+yy-2, gx=x0+xx-2;
        ti[yy][xx] = ((unsigned)gy<HH && (unsigned)gx<WW) ? g_inp[(size_t)n*HWSZ + gy*WW + gx] : 0.f;
    }
    float acc[5][4];
    #pragma unroll
    for (int t=0;t<5;t++)
        #pragma unroll
        for (int k=0;k<4;k++) acc[t][k]=0.f;

    for (int c=0;c<9;c++){
        __syncthreads();
        for (int i=tid;i<340;i+=64){
            int yy=i/34, xx=i%34;
            int gy=y0+yy-1, gx=x0+xx-1;
            t9[yy][xx] = ((unsigned)gy<HH && (unsigned)gx<WW) ? g_xm9[((size_t)(n*9+c))*HWSZ + gy*WW + gx] : 0.f;
        }
        __syncthreads();
        #pragma unroll
        for (int r=0;r<3;r++)
        #pragma unroll
        for (int s=0;s<3;s++){
            float wv[5];
            #pragma unroll
            for (int t=0;t<5;t++) wv[t] = wsm[t*81 + c*9 + r*3 + s];
            #pragma unroll
            for (int k=0;k<4;k++){
                float v = t9[threadIdx.y + r][threadIdx.x*4 + k + s];
                #pragma unroll
                for (int t=0;t<5;t++) acc[t][k] = fmaf(wv[t], v, acc[t][k]);
            }
        }
    }
    #pragma unroll
    for (int t=0;t<5;t++){
        const int tt = grp*5 + t;   // i = grp, j = t
        #pragma unroll
        for (int k=0;k<4;k++){
            int lx = threadIdx.x*4 + k;
            float ctr = ti[threadIdx.y+2][lx+2];
            float aff = ti[threadIdx.y+grp][lx+t] * ctr;
            g_xm25[((size_t)(n*25+tt))*HWSZ + (size_t)(y0+threadIdx.y)*WW + x0 + lx] = aff + acc[t][k];
        }
    }
}

// ---------------- conv4d + affinity reduce + seg output ------------------------
__global__ __launch_bounds__(256) void final_k(const float* __restrict__ d4,
                                               float* __restrict__ segout)
{
    __shared__ float t25[25][10][34];
    __shared__ float ti[12][36];
    __shared__ float wsm[81];
    const int n = blockIdx.z;
    const int x0 = blockIdx.x*32, y0 = blockIdx.y*8;
    const int tid = threadIdx.y*32 + threadIdx.x;
    if (tid < 81) wsm[tid] = d4[tid];
    for (int i = tid; i < 25*340; i += 256){
        int c = i/340, rr = i - c*340, yy = rr/34, xx = rr%34;
        int gy=y0+yy-1, gx=x0+xx-1;
        t25[c][yy][xx] = ((unsigned)gy<HH && (unsigned)gx<WW) ? g_xm25[((size_t)(n*25+c))*HWSZ + gy*WW + gx] : 0.f;
    }
    for (int i=tid;i<432;i+=256){
        int yy=i/36, xx=i%36;
        int gy=y0+yy-2, gx=x0+xx-2;
        ti[yy][xx] = ((unsigned)gy<HH && (unsigned)gx<WW) ? g_inp[(size_t)n*HWSZ + gy*WW + gx] : 0.f;
    }
    __syncthreads();

    float kacc[25];
    #pragma unroll
    for (int t=0;t<25;t++) kacc[t]=0.f;

    #pragma unroll
    for (int r=0;r<3;r++)
    #pragma unroll
    for (int s=0;s<3;s++){
        float wv[9];
        #pragma unroll
        for (int p=0;p<3;p++)
        #pragma unroll
        for (int q=0;q<3;q++) wv[p*3+q] = wsm[((p*3+q)*3+r)*3 + s];
        float L[25];
        #pragma unroll
        for (int u=0;u<5;u++)
        #pragma unroll
        for (int v=0;v<5;v++) L[u*5+v] = t25[u*5+v][threadIdx.y+r][threadIdx.x+s];
        #pragma unroll
        for (int d=0;d<5;d++)
        #pragma unroll
        for (int e=0;e<5;e++)
        #pragma unroll
        for (int p=0;p<3;p++){
            int u = d-1+p; if (u < 0 || u > 4) continue;
            #pragma unroll
            for (int q=0;q<3;q++){
                int v = e-1+q; if (v < 0 || v > 4) continue;
                kacc[d*5+e] = fmaf(L[u*5+v], wv[p*3+q], kacc[d*5+e]);
            }
        }
    }
    float sum = 0.f;
    #pragma unroll
    for (int ii=0;ii<5;ii++)
    #pragma unroll
    for (int jj=0;jj<5;jj++)
        sum = fmaf(ti[threadIdx.y+ii][threadIdx.x+jj], kacc[ii*5+jj], sum);

    float o = sum / 25.0f;
    int idx = (y0+threadIdx.y)*WW + x0 + threadIdx.x;
    segout[((size_t)(n*2+0))*HWSZ + idx] = 1.0f - o;
    segout[((size_t)(n*2+1))*HWSZ + idx] = o;
}

// ---------------- top-k threshold: radix select on float keys ------------------
__device__ __forceinline__ unsigned f2key(float f){
    unsigned u = __float_as_uint(f);
    return (u & 0x80000000u) ? ~u : (u | 0x80000000u);
}
__device__ __forceinline__ float key2f(unsigned k){
    unsigned u = (k & 0x80000000u) ? (k & 0x7fffffffu) : ~k;
    return __uint_as_float(u);
}

__global__ void thr_init_k(const float* __restrict__ ratio)
{
    int t = threadIdx.x;
    unsigned* hflat = &g_hist[0][0];
    for (int i=t;i<4*256;i+=256) hflat[i]=0u;
    if (t < 4){
        int n = t >> 1;
        float fp = floorf(ratio[n]*(float)HWSZ);
        int k = (int)floorf(fp*0.1f);
        int idx = k-1; if (idx < 0) idx = 0;
        g_remain[t] = idx;
        g_prefix[t] = 0u;
    }
}

__global__ __launch_bounds__(256) void hist_k(const float* __restrict__ seg, int shift)
{
    __shared__ unsigned hh[256];
    const int j = blockIdx.y;
    hh[threadIdx.x]=0u;
    __syncthreads();
    unsigned pfx = g_prefix[j];
    unsigned mask = (shift==24) ? 0u : (0xFFFFFFFFu << (shift+8));
    const float* p = seg + (size_t)j*HWSZ;
    for (int i = blockIdx.x*256 + threadIdx.x; i < HWSZ; i += 64*256){
        unsigned key = f2key(p[i]);
        if ((key & mask) == pfx) atomicAdd(&hh[(key>>shift)&255u], 1u);
    }
    __syncthreads();
    if (hh[threadIdx.x]) atomicAdd(&g_hist[j][threadIdx.x], hh[threadIdx.x]);
}

__global__ void select_k(int shift, int last)
{
    int j = threadIdx.x;
    if (j >= 4) return;
    int rem = g_remain[j];
    unsigned pfx = g_prefix[j];
    int done = 0;
    for (int b=255;b>=0;b--){
        unsigned c = g_hist[j][b];
        if (!done){
            if ((int)c > rem){ pfx |= ((unsigned)b)<<shift; done=1; }
            else rem -= (int)c;
        }
        g_hist[j][b]=0u;
    }
    g_prefix[j]=pfx; g_remain[j]=rem;
    if (last) g_thr[j] = key2f(pfx);
}

__global__ __launch_bounds__(256) void erase_k(const float* __restrict__ seg,
                                               const float* __restrict__ x)
{
    int i = blockIdx.x*256 + threadIdx.x;
    if (i >= NHW) return;
    int n = i / HWSZ, r = i - n*HWSZ;
    float t0 = g_thr[n*2+0], t1 = g_thr[n*2+1];
    bool m = (seg[((size_t)(n*2+0))*HWSZ + r] > t0) || (seg[((size_t)(n*2+1))*HWSZ + r] > t1);
    #pragma unroll
    for (int c=0;c<3;c++)
        g_img2[((size_t)(n*3+c))*HWSZ + r] = m ? 0.f : x[((size_t)(n*3+c))*HWSZ + r];
}

// ---------------- host orchestration -------------------------------------------
struct Ptrs { float *feat, *aux, *auxb1, *z, *scale1, *shift1, *scale2, *shift2; };

static void run_pipeline(const float* img, float* seg_out,
                         const float* w1, const float* wa, const float* wout,
                         const float* b1w, const float* b1g, const float* b1b,
                         const float* b2w, const float* b2g, const float* b2b,
                         const float* d0w, const float* d1w, const float* d4w,
                         const Ptrs& P)
{
    dim3 blk(32,8);
    conv3x3_k<3,true ><<<dim3(16,16,NB*4), blk>>>(img,    w1,  P.feat,  4);
    conv3x3_k<3,true ><<<dim3(16,16,NB*4), blk>>>(img,    wa,  P.aux,   4);
    conv3x3_k<32,false><<<dim3(16,16,NB*4), blk>>>(P.aux, b1w, P.auxb1, 4);
    stats1_k<<<dim3(PARTS,32), 256>>>(P.auxb1, 32);
    stats2_k<<<32,128>>>(b1g, b1b, P.scale1, P.shift1);
    b2_k<<<(NHW+255)/256, 256>>>(b2w);
    stats1_k<<<dim3(PARTS,1), 256>>>(P.z, 1);
    stats2_k<<<1,128>>>(b2g, b2b, P.scale2, P.shift2);
    wout_inp_k<<<dim3(16,16,NB), blk>>>(P.feat, wout);
    xm9_k<<<dim3(16,64,NB), blk>>>(d0w);
    xm25_k<<<dim3(16,64,NB*5), dim3(8,8)>>>(d1w);
    final_k<<<dim3(16,64,NB), blk>>>(d4w, seg_out);
}

extern "C" void kernel_launch(void* const* d_in, const int* in_sizes, int n_in,
                              void* d_out, int out_size)
{
    const float* x     = (const float*)d_in[0];
    const float* ratio = (const float*)d_in[1];
    const float* w1    = (const float*)d_in[2];
    const float* wa    = (const float*)d_in[3];
    const float* wout  = (const float*)d_in[4];
    const float* b1w   = (const float*)d_in[5];
    const float* b1g   = (const float*)d_in[6];
    const float* b1b   = (const float*)d_in[7];
    const float* b2w   = (const float*)d_in[8];
    const float* b2g   = (const float*)d_in[9];
    const float* b2b   = (const float*)d_in[10];
    const float* d0w   = (const float*)d_in[11];
    const float* d1w   = (const float*)d_in[12];
    const float* d4w   = (const float*)d_in[13];
    float* out = (float*)d_out;

    Ptrs P;
    void* p;
    cudaGetSymbolAddress(&p, g_feat);   P.feat   = (float*)p;
    cudaGetSymbolAddress(&p, g_aux);    P.aux    = (float*)p;
    cudaGetSymbolAddress(&p, g_auxb1);  P.auxb1  = (float*)p;
    cudaGetSymbolAddress(&p, g_z);      P.z      = (float*)p;
    cudaGetSymbolAddress(&p, g_scale1); P.scale1 = (float*)p;
    cudaGetSymbolAddress(&p, g_shift1); P.shift1 = (float*)p;
    cudaGetSymbolAddress(&p, g_scale2); P.scale2 = (float*)p;
    cudaGetSymbolAddress(&p, g_shift2); P.shift2 = (float*)p;
    float* img2; cudaGetSymbolAddress(&p, g_img2); img2 = (float*)p;

    // pipeline 1 -> x1 (first half of output)
    run_pipeline(x, out, w1, wa, wout, b1w, b1g, b1b, b2w, b2g, b2b,
                 d0w, d1w, d4w, P);

    // erasing: per-(n,c) radix select of the idx-th largest seg value
    thr_init_k<<<1,256>>>(ratio);
    for (int pass=0; pass<4; ++pass){
        int shift = 24 - 8*pass;
        hist_k<<<dim3(64,4), 256>>>(out, shift);
        select_k<<<1,4>>>(shift, pass==3 ? 1 : 0);
    }
    erase_k<<<(NHW+255)/256, 256>>>(out, x);

    // pipeline 2 -> x2 (second half of output)
    run_pipeline(img2, out + (size_t)NB*2*HWSZ, w1, wa, wout,
                 b1w, b1g, b1b, b2w, b2g, b2b, d0w, d1w, d4w, P);
}